// round 4
// baseline (speedup 1.0000x reference)
#include <cuda_runtime.h>
#include <math.h>
#include <stdint.h>

#define NC 21
#define MAXN 8732
#define OBJ 16
#define FULLW 0xffffffffu
#define TPB 1024
#define TILE 1024

// -------- global accumulators (statically zeroed; last CTA resets them) ----
__device__ double   g_loss_l     = 0.0;
__device__ double   g_loss_c     = 0.0;
__device__ int      g_npos_total = 0;
__device__ unsigned g_ticket     = 0;

// dynamic smem layout:
//   s_conf[2] : 2 * TILE*NC floats (2*86016 B) double-buffered conf tiles
//   s_u       : MAXN u32           (34928 B)   lc bits (0 for positives)
//   s_cls     : MAXN u8            ( 8732 B)
//   s_bti     : MAXN u8            ( 8732 B)
#define BUF_BYTES (TILE*NC*4)
#define DYN_BYTES (2*BUF_BYTES + MAXN*4 + MAXN + MAXN)

extern __shared__ unsigned char s_dyn[];

__device__ __forceinline__ void cpa16(unsigned saddr, const void* g) {
    asm volatile("cp.async.cg.shared.global [%0], [%1], 16;" :: "r"(saddr), "l"(g));
}
__device__ __forceinline__ void cpa4(unsigned saddr, const void* g) {
    asm volatile("cp.async.ca.shared.global [%0], [%1], 4;" :: "r"(saddr), "l"(g));
}
__device__ __forceinline__ void cpa_commit() {
    asm volatile("cp.async.commit_group;");
}
__device__ __forceinline__ unsigned smem_u32(const void* p) {
    return (unsigned)__cvta_generic_to_shared(p);
}

__global__ void __launch_bounds__(TPB, 1) fused_kernel(
        const float* __restrict__ loc,
        const float* __restrict__ conf,
        const float* __restrict__ targets,
        const float* __restrict__ priors,
        int N, int B, float* __restrict__ out)
{
    const int b    = blockIdx.x;
    const int tid  = threadIdx.x;
    const int lane = tid & 31;
    const int warp = tid >> 5;

    float*          s_conf0 = (float*)s_dyn;
    float*          s_conf1 = (float*)(s_dyn + BUF_BYTES);
    unsigned*       s_u     = (unsigned*)(s_dyn + 2*BUF_BYTES);
    unsigned char*  s_cls   = (unsigned char*)(s_u + MAXN);
    unsigned char*  s_bti   = s_cls + MAXN;

    __shared__ float4 s_tv[OBJ];          // (x1,y1,x2,y2)
    __shared__ int    s_lab[OBJ];
    __shared__ unsigned long long s_key[OBJ];
    __shared__ unsigned s_hist[256];
    __shared__ unsigned s_prefix, s_remK;
    __shared__ double s_rd[32], s_rd2[32];
    __shared__ int    s_ri[32];
    __shared__ int    s_npb;

    const int ntiles = (N + TILE - 1) / TILE;
    const float* confb = conf + (size_t)b * N * NC;

    // helper lambda: issue cp.async for tile t into buffer buf
    auto prefetch = [&](int t, float* buf) {
        int rows = min(TILE, N - t * TILE);
        int nfl  = rows * NC;
        const float* src = confb + (size_t)t * TILE * NC;
        int n4 = nfl >> 2;
        unsigned sbase = smem_u32(buf);
        const float4* s4 = (const float4*)src;
        for (int k = tid; k < n4; k += TPB)
            cpa16(sbase + k * 16, s4 + k);
        for (int k = (n4 << 2) + tid; k < nfl; k += TPB)
            cpa4(sbase + k * 4, src + k);
        cpa_commit();
    };

    // kick off tile 0 load immediately — overlaps with the match phase
    prefetch(0, s_conf0);

    // ================= phase 1: match =================
    if (tid < OBJ) {
        const float* tr = targets + ((size_t)b * OBJ + tid) * 5;
        s_tv[tid] = make_float4(tr[0], tr[1], tr[2], tr[3]);
        s_lab[tid] = (int)tr[4];
        s_key[tid] = 0ULL;
    }
    __syncthreads();

    {
        // per-truth best key: (iou_bits<<32)|(~i) -> max = largest IoU,
        // smallest prior index on ties (== jnp.argmax first-max).
        unsigned long long lkey[OBJ];
        #pragma unroll
        for (int j = 0; j < OBJ; j++) lkey[j] = 0ULL;

        for (int i = tid; i < N; i += TPB) {
            float4 p = ((const float4*)priors)[i];
            float px1 = p.x - p.z * 0.5f, py1 = p.y - p.w * 0.5f;
            float px2 = p.x + p.z * 0.5f, py2 = p.y + p.w * 0.5f;
            float parea = (px2 - px1) * (py2 - py1);

            float best = -1.0f; int bj = 0;
            #pragma unroll
            for (int j = 0; j < OBJ; j++) {
                float4 tv = s_tv[j];                       // LDS.128 broadcast
                float tarea = (tv.z - tv.x) * (tv.w - tv.y);
                float ix = fminf(tv.z, px2) - fmaxf(tv.x, px1);
                float iy = fminf(tv.w, py2) - fmaxf(tv.y, py1);
                ix = fmaxf(ix, 0.0f); iy = fmaxf(iy, 0.0f);
                float inter = ix * iy;
                float iou = __fdividef(inter, tarea + parea - inter);
                if (iou > best) { best = iou; bj = j; }    // strict > = first max
                unsigned long long key =
                    (((unsigned long long)__float_as_uint(iou)) << 32) |
                    (unsigned long long)(0xFFFFFFFFu - (unsigned)i);
                if (key > lkey[j]) lkey[j] = key;
            }
            s_cls[i] = (best < 0.5f) ? 0 : (unsigned char)(s_lab[bj] + 1);
            s_bti[i] = (unsigned char)bj;
        }

        #pragma unroll
        for (int j = 0; j < OBJ; j++) {
            unsigned long long k = lkey[j];
            #pragma unroll
            for (int off = 16; off > 0; off >>= 1) {
                unsigned long long o = __shfl_down_sync(FULLW, k, off);
                if (o > k) k = o;
            }
            if (lane == 0) atomicMax(&s_key[j], k);
        }
    }
    __syncthreads();

    // forced matches: later j wins (== fori_loop), forced cls regardless of iou
    if (tid == 0) {
        #pragma unroll
        for (int j = 0; j < OBJ; j++) {
            unsigned idx = 0xFFFFFFFFu - (unsigned)(s_key[j] & 0xFFFFFFFFu);
            s_cls[idx] = (unsigned char)(s_lab[j] + 1);
            s_bti[idx] = (unsigned char)j;
        }
    }
    __syncthreads();

    // ================= phase 2: per-prior losses (pipelined conf stream) ====
    double ll = 0.0, lcp = 0.0; int np = 0;

    for (int t = 0; t < ntiles; t++) {
        float* cur = (t & 1) ? s_conf1 : s_conf0;
        if (t + 1 < ntiles) {
            prefetch(t + 1, (t & 1) ? s_conf0 : s_conf1);
            asm volatile("cp.async.wait_group 1;");
        } else {
            asm volatile("cp.async.wait_group 0;");
        }
        __syncthreads();                         // tile t visible to all

        int t0  = t * TILE;
        int cnt = min(TILE, N - t0);
        if (tid < cnt) {
            int i = t0 + tid;
            int cls = s_cls[i];
            const float* row = cur + tid * NC;   // stride 21: conflict-free
            float m = row[0];
            #pragma unroll
            for (int c = 1; c < NC; c++) m = fmaxf(m, row[c]);
            float s = 0.0f;
            #pragma unroll
            for (int c = 0; c < NC; c++) s += __expf(row[c] - m);
            float lse = m + __logf(s);
            float lca = lse - row[cls];
            bool pos = (cls > 0);
            s_u[i] = pos ? 0u : __float_as_uint(lca);   // lc >= 0: monotone bits

            if (pos) {
                lcp += (double)lca; np++;
                float4 tv = s_tv[s_bti[i]];
                float4 p  = ((const float4*)priors)[i];
                float gx = ((tv.x + tv.z) * 0.5f - p.x) / (0.1f * p.z);
                float gy = ((tv.y + tv.w) * 0.5f - p.y) / (0.1f * p.w);
                float gw = logf((tv.z - tv.x) / p.z) * 5.0f;
                float gh = logf((tv.w - tv.y) / p.w) * 5.0f;
                float4 l = ((const float4*)loc)[(size_t)b * N + i];
                float d;
                d = l.x - gx; ll += (fabsf(d) < 1.0f) ? 0.5f*d*d : fabsf(d) - 0.5f;
                d = l.y - gy; ll += (fabsf(d) < 1.0f) ? 0.5f*d*d : fabsf(d) - 0.5f;
                d = l.z - gw; ll += (fabsf(d) < 1.0f) ? 0.5f*d*d : fabsf(d) - 0.5f;
                d = l.w - gh; ll += (fabsf(d) < 1.0f) ? 0.5f*d*d : fabsf(d) - 0.5f;
            }
        }
        __syncthreads();                         // done reading cur before reuse
    }

    // block reduce (ll, lcp, np)
    #pragma unroll
    for (int off = 16; off > 0; off >>= 1) {
        ll  += __shfl_down_sync(FULLW, ll,  off);
        lcp += __shfl_down_sync(FULLW, lcp, off);
        np  += __shfl_down_sync(FULLW, np,  off);
    }
    if (lane == 0) { s_rd[warp] = ll; s_rd2[warp] = lcp; s_ri[warp] = np; }
    __syncthreads();

    double bll = 0.0, blc = 0.0; int bnp = 0;
    if (warp == 0) {
        bll = s_rd[lane]; blc = s_rd2[lane]; bnp = s_ri[lane];
        #pragma unroll
        for (int off = 16; off > 0; off >>= 1) {
            bll += __shfl_down_sync(FULLW, bll, off);
            blc += __shfl_down_sync(FULLW, blc, off);
            bnp += __shfl_down_sync(FULLW, bnp, off);
        }
        if (lane == 0) s_npb = bnp;
    }
    __syncthreads();

    int npb = s_npb;
    int K = min(3 * npb, N - 1);

    // ================= phase 3: hard-negative radix top-K on smem ==========
    double negsum = 0.0;   // valid on tid 0 after this phase

    if (K > 0) {
        if (tid == 0) { s_prefix = 0u; s_remK = (unsigned)K; }
        __syncthreads();

        const int iters = (N + TPB - 1) / TPB;
        #pragma unroll
        for (int pass = 0; pass < 4; pass++) {
            int shift = 24 - pass * 8;
            unsigned maskAbove = (pass == 0) ? 0u : (0xFFFFFFFFu << (shift + 8));
            if (tid < 256) s_hist[tid] = 0u;
            __syncthreads();
            unsigned prefix = s_prefix;
            for (int it = 0; it < iters; it++) {
                int i = it * TPB + tid;
                unsigned u = (i < N) ? s_u[i] : 0u;
                bool act = (i < N) && ((u & maskAbove) == prefix);
                unsigned amask = __ballot_sync(FULLW, act);
                if (act) {
                    unsigned bin = (u >> shift) & 255u;
                    unsigned mm = __match_any_sync(amask, bin);   // warp-aggregate
                    if (lane == (__ffs(mm) - 1))
                        atomicAdd(&s_hist[bin], (unsigned)__popc(mm));
                }
            }
            __syncthreads();
            // warp-0 register suffix scan over 256 bins (8 bins/lane)
            if (tid < 32) {
                unsigned h[8]; unsigned lsum = 0;
                #pragma unroll
                for (int k = 0; k < 8; k++) { h[k] = s_hist[tid*8 + k]; lsum += h[k]; }
                unsigned suf = lsum;
                #pragma unroll
                for (int off = 1; off < 32; off <<= 1) {
                    unsigned v = __shfl_down_sync(FULLW, suf, off);
                    if (tid + off < 32) suf += v;
                }
                unsigned remK = s_remK;
                unsigned acc = suf - lsum;        // count in higher bins
                #pragma unroll
                for (int k = 7; k >= 0; k--) {
                    if (acc < remK && acc + h[k] >= remK) {
                        s_prefix = prefix | ((unsigned)(tid*8 + k) << shift);
                        s_remK   = remK - acc;
                    }
                    acc += h[k];
                }
            }
            __syncthreads();
        }

        unsigned tbits = s_prefix;                // K-th largest value bits
        double lsum = 0.0; unsigned cgt = 0;
        for (int i = tid; i < N; i += TPB) {
            unsigned u = s_u[i];
            if (u > tbits) { lsum += (double)__uint_as_float(u); cgt++; }
        }
        #pragma unroll
        for (int off = 16; off > 0; off >>= 1) {
            lsum += __shfl_down_sync(FULLW, lsum, off);
            cgt  += __shfl_down_sync(FULLW, cgt,  off);
        }
        if (lane == 0) { s_rd[warp] = lsum; s_ri[warp] = (int)cgt; }
        __syncthreads();
        if (warp == 0) {
            double a = s_rd[lane];
            int    c = s_ri[lane];
            #pragma unroll
            for (int off = 16; off > 0; off >>= 1) {
                a += __shfl_down_sync(FULLW, a, off);
                c += __shfl_down_sync(FULLW, c, off);
            }
            if (lane == 0) {
                unsigned m = (unsigned)K - (unsigned)c;   // tie slots worth t each
                negsum = a + (double)m * (double)__uint_as_float(tbits);
            }
        }
    }

    // ================= phase 4: accumulate + self-finalize =================
    if (tid == 0) {
        atomicAdd(&g_loss_l, bll);
        atomicAdd(&g_loss_c, blc + negsum);
        atomicAdd(&g_npos_total, npb);
        __threadfence();
        unsigned t = atomicAdd(&g_ticket, 1u);
        if (t == (unsigned)B - 1u) {          // last CTA: finalize + reset
            __threadfence();
            double L = atomicAdd(&g_loss_l, 0.0);
            double C = atomicAdd(&g_loss_c, 0.0);
            int    n = atomicAdd(&g_npos_total, 0);
            float  nf = (float)n;
            out[0] = (float)L / nf;
            out[1] = (float)C / nf;
            g_loss_l = 0.0; g_loss_c = 0.0; g_npos_total = 0;
            __threadfence();
            g_ticket = 0u;
        }
    }
}

// ---------------- launch ----------------
extern "C" void kernel_launch(void* const* d_in, const int* in_sizes, int n_in,
                              void* d_out, int out_size) {
    const float* loc     = (const float*)d_in[0];
    const float* conf    = (const float*)d_in[1];
    const float* targets = (const float*)d_in[2];
    const float* priors  = (const float*)d_in[3];
    int N = in_sizes[3] / 4;
    int B = in_sizes[0] / (4 * N);

    cudaFuncSetAttribute(fused_kernel,
                         cudaFuncAttributeMaxDynamicSharedMemorySize, DYN_BYTES);
    fused_kernel<<<B, TPB, DYN_BYTES>>>(loc, conf, targets, priors, N, B,
                                        (float*)d_out);
}

// round 5
// speedup vs baseline: 1.2380x; 1.2380x over previous
#include <cuda_runtime.h>
#include <math.h>
#include <stdint.h>

#define NC 21
#define MAXN 8732
#define MAXB 128
#define OBJ 16
#define FULLW 0xffffffffu
#define ROWS 256            // rows per stream CTA

// -------- global accumulators / scratch (statically zeroed; select resets) --
__device__ double   g_loss_l     = 0.0;
__device__ double   g_loss_c     = 0.0;
__device__ int      g_npos_total = 0;
__device__ int      g_npos_b[MAXB];          // zero-init
__device__ unsigned g_ticket     = 0;
__device__ unsigned g_lc [MAXB * MAXN];      // lc bits (0 for positives)
__device__ unsigned short g_cb[MAXB * MAXN]; // cls | (bti<<8)

// ==================== kernel A: match (one CTA per batch) ====================
__global__ void __launch_bounds__(512) match_kernel(
        const float* __restrict__ targets,
        const float* __restrict__ priors,
        int N) {
    const int b    = blockIdx.x;
    const int tid  = threadIdx.x;
    const int lane = tid & 31;

    __shared__ float4 s_tv[OBJ];
    __shared__ int    s_lab[OBJ];
    __shared__ unsigned long long s_key[OBJ];

    if (tid < OBJ) {
        const float* tr = targets + ((size_t)b * OBJ + tid) * 5;
        s_tv[tid]  = make_float4(tr[0], tr[1], tr[2], tr[3]);
        s_lab[tid] = (int)tr[4];
        s_key[tid] = 0ULL;
    }
    __syncthreads();

    // per-truth best key: (iou_bits<<32)|(~i) -> max = largest IoU,
    // smallest prior index on ties (== jnp.argmax first-max semantics).
    unsigned long long lkey[OBJ];
    #pragma unroll
    for (int j = 0; j < OBJ; j++) lkey[j] = 0ULL;

    for (int i = tid; i < N; i += 512) {
        float4 p = ((const float4*)priors)[i];
        float px1 = p.x - p.z * 0.5f, py1 = p.y - p.w * 0.5f;
        float px2 = p.x + p.z * 0.5f, py2 = p.y + p.w * 0.5f;
        float parea = (px2 - px1) * (py2 - py1);

        float best = -1.0f; int bj = 0;
        #pragma unroll
        for (int j = 0; j < OBJ; j++) {
            float4 tv = s_tv[j];
            float tarea = (tv.z - tv.x) * (tv.w - tv.y);
            float ix = fminf(tv.z, px2) - fmaxf(tv.x, px1);
            float iy = fminf(tv.w, py2) - fmaxf(tv.y, py1);
            ix = fmaxf(ix, 0.0f); iy = fmaxf(iy, 0.0f);
            float inter = ix * iy;
            float iou = __fdividef(inter, tarea + parea - inter);
            if (iou > best) { best = iou; bj = j; }        // first max over j
            unsigned long long key =
                (((unsigned long long)__float_as_uint(iou)) << 32) |
                (unsigned long long)(0xFFFFFFFFu - (unsigned)i);
            if (key > lkey[j]) lkey[j] = key;
        }
        int cls = (best < 0.5f) ? 0 : (s_lab[bj] + 1);
        g_cb[(size_t)b * N + i] = (unsigned short)(cls | (bj << 8));
    }

    #pragma unroll
    for (int j = 0; j < OBJ; j++) {
        unsigned long long k = lkey[j];
        #pragma unroll
        for (int off = 16; off > 0; off >>= 1) {
            unsigned long long o = __shfl_down_sync(FULLW, k, off);
            if (o > k) k = o;
        }
        if (lane == 0) atomicMax(&s_key[j], k);
    }
    __syncthreads();

    // forced matches: later j wins (== fori_loop); forced cls regardless of iou
    if (tid == 0) {
        #pragma unroll
        for (int j = 0; j < OBJ; j++) {
            unsigned idx = 0xFFFFFFFFu - (unsigned)(s_key[j] & 0xFFFFFFFFu);
            g_cb[(size_t)b * N + idx] =
                (unsigned short)((s_lab[j] + 1) | (j << 8));
        }
    }
}

// ============ kernel B: conf stream + per-prior losses (massively parallel) ==
__global__ void __launch_bounds__(ROWS) loss_kernel(
        const float* __restrict__ loc,
        const float* __restrict__ conf,
        const float* __restrict__ targets,
        const float* __restrict__ priors,
        int N) {
    const int b    = blockIdx.y;
    const int r0   = blockIdx.x * ROWS;
    const int tid  = threadIdx.x;
    const int lane = tid & 31;
    const int warp = tid >> 5;

    __shared__ float  s_conf[ROWS * NC];     // 21504 B
    __shared__ double s_rd[8], s_rd2[8];
    __shared__ int    s_ri[8];

    const int cnt = min(ROWS, N - r0);
    const int nfl = cnt * NC;

    {   // coalesced float4 staging (base always 16B-aligned; see launch math)
        const float4* s4 = (const float4*)(conf + ((size_t)b * N + r0) * NC);
        float4* d4 = (float4*)s_conf;
        int n4 = nfl >> 2;
        #pragma unroll 6
        for (int k = tid; k < n4; k += ROWS) d4[k] = s4[k];
        for (int k = (n4 << 2) + tid; k < nfl; k += ROWS)
            s_conf[k] = ((const float*)s4)[k];
    }
    __syncthreads();

    double ll = 0.0, lcp = 0.0; int np = 0;

    if (tid < cnt) {
        const int i = r0 + tid;
        const size_t gi = (size_t)b * N + i;
        unsigned short cb = g_cb[gi];
        int cls = cb & 0xFF;

        float r[NC];
        const float* row = s_conf + tid * NC;      // stride 21: conflict-free
        #pragma unroll
        for (int c = 0; c < NC; c++) r[c] = row[c];
        float m = r[0];
        #pragma unroll
        for (int c = 1; c < NC; c++) m = fmaxf(m, r[c]);
        float s = 0.0f;
        #pragma unroll
        for (int c = 0; c < NC; c++) s += __expf(r[c] - m);
        float lse = m + __logf(s);
        float lca = lse - row[cls];                // dynamic idx via 1 LDS
        bool pos = (cls > 0);
        g_lc[gi] = pos ? 0u : __float_as_uint(lca);   // lc >= 0: monotone bits

        if (pos) {
            lcp = (double)lca; np = 1;
            int tj = cb >> 8;
            const float* tr = targets + ((size_t)b * OBJ + tj) * 5;
            float tx1 = tr[0], ty1 = tr[1], tx2 = tr[2], ty2 = tr[3];
            float4 p = ((const float4*)priors)[i];
            float gx = ((tx1 + tx2) * 0.5f - p.x) / (0.1f * p.z);
            float gy = ((ty1 + ty2) * 0.5f - p.y) / (0.1f * p.w);
            float gw = logf((tx2 - tx1) / p.z) * 5.0f;
            float gh = logf((ty2 - ty1) / p.w) * 5.0f;
            float4 l = ((const float4*)loc)[gi];
            float d;
            d = l.x - gx; ll += (fabsf(d) < 1.0f) ? 0.5f*d*d : fabsf(d) - 0.5f;
            d = l.y - gy; ll += (fabsf(d) < 1.0f) ? 0.5f*d*d : fabsf(d) - 0.5f;
            d = l.z - gw; ll += (fabsf(d) < 1.0f) ? 0.5f*d*d : fabsf(d) - 0.5f;
            d = l.w - gh; ll += (fabsf(d) < 1.0f) ? 0.5f*d*d : fabsf(d) - 0.5f;
        }
    }

    // block reduce, then skip-if-zero atomics (most CTAs have 0-2 positives)
    #pragma unroll
    for (int off = 16; off > 0; off >>= 1) {
        ll  += __shfl_down_sync(FULLW, ll,  off);
        lcp += __shfl_down_sync(FULLW, lcp, off);
        np  += __shfl_down_sync(FULLW, np,  off);
    }
    if (lane == 0) { s_rd[warp] = ll; s_rd2[warp] = lcp; s_ri[warp] = np; }
    __syncthreads();
    if (warp == 0 && lane < 8) {
        double a = s_rd[lane], c = s_rd2[lane]; int n = s_ri[lane];
        #pragma unroll
        for (int off = 4; off > 0; off >>= 1) {
            a += __shfl_down_sync(0xFFu, a, off);
            c += __shfl_down_sync(0xFFu, c, off);
            n += __shfl_down_sync(0xFFu, n, off);
        }
        if (lane == 0 && n) {
            atomicAdd(&g_loss_l, a);
            atomicAdd(&g_loss_c, c);
            atomicAdd(&g_npos_total, n);
            atomicAdd(&g_npos_b[b], n);
        }
    }
}

// ====== kernel C: hard-negative radix top-K per batch + finalize =============
__global__ void __launch_bounds__(1024) select_kernel(int N, int B,
                                                      float* __restrict__ out) {
    const int b    = blockIdx.x;
    const int tid  = threadIdx.x;
    const int lane = tid & 31;
    const int warp = tid >> 5;

    __shared__ unsigned s_u[MAXN];
    __shared__ unsigned s_hist[256];
    __shared__ unsigned s_prefix, s_remK;
    __shared__ double   s_d[32];
    __shared__ unsigned s_c[32];

    {   // vectorized load (N*4B base aligned; tail handled scalar)
        const uint4* src4 = (const uint4*)(g_lc + (size_t)b * N);
        uint4* dst4 = (uint4*)s_u;
        int n4 = N >> 2;
        for (int k = tid; k < n4; k += 1024) dst4[k] = src4[k];
        for (int k = (n4 << 2) + tid; k < N; k += 1024)
            s_u[k] = g_lc[(size_t)b * N + k];
    }

    const int K = min(3 * g_npos_b[b], N - 1);
    double negsum = 0.0;                      // valid on tid 0 afterwards

    if (K > 0) {
        if (tid == 0) { s_prefix = 0u; s_remK = (unsigned)K; }
        __syncthreads();

        const int iters = (N + 1023) >> 10;
        #pragma unroll
        for (int pass = 0; pass < 4; pass++) {
            int shift = 24 - pass * 8;
            unsigned maskAbove = (pass == 0) ? 0u : (0xFFFFFFFFu << (shift + 8));
            if (tid < 256) s_hist[tid] = 0u;
            __syncthreads();
            unsigned prefix = s_prefix;
            for (int it = 0; it < iters; it++) {
                int i = (it << 10) + tid;
                unsigned u = (i < N) ? s_u[i] : 0u;
                bool act = (i < N) && ((u & maskAbove) == prefix);
                unsigned amask = __ballot_sync(FULLW, act);
                if (act) {
                    unsigned bin = (u >> shift) & 255u;
                    unsigned mm = __match_any_sync(amask, bin);  // warp-aggregate
                    if (lane == (__ffs(mm) - 1))
                        atomicAdd(&s_hist[bin], (unsigned)__popc(mm));
                }
            }
            __syncthreads();
            // warp-0 register suffix scan over 256 bins (8 bins/lane)
            if (tid < 32) {
                unsigned h[8]; unsigned lsum = 0;
                #pragma unroll
                for (int k = 0; k < 8; k++) { h[k] = s_hist[tid*8+k]; lsum += h[k]; }
                unsigned suf = lsum;
                #pragma unroll
                for (int off = 1; off < 32; off <<= 1) {
                    unsigned v = __shfl_down_sync(FULLW, suf, off);
                    if (tid + off < 32) suf += v;
                }
                unsigned remK = s_remK;
                unsigned acc = suf - lsum;         // count in higher bins
                #pragma unroll
                for (int k = 7; k >= 0; k--) {
                    if (acc < remK && acc + h[k] >= remK) {
                        s_prefix = prefix | ((unsigned)(tid*8+k) << shift);
                        s_remK   = remK - acc;
                    }
                    acc += h[k];
                }
            }
            __syncthreads();
        }

        unsigned tbits = s_prefix;                 // K-th largest value bits
        double lsum = 0.0; unsigned cgt = 0;
        for (int i = tid; i < N; i += 1024) {
            unsigned u = s_u[i];
            if (u > tbits) { lsum += (double)__uint_as_float(u); cgt++; }
        }
        #pragma unroll
        for (int off = 16; off > 0; off >>= 1) {
            lsum += __shfl_down_sync(FULLW, lsum, off);
            cgt  += __shfl_down_sync(FULLW, cgt,  off);
        }
        if (lane == 0) { s_d[warp] = lsum; s_c[warp] = cgt; }
        __syncthreads();
        if (warp == 0) {
            double a = s_d[lane]; unsigned c = s_c[lane];
            #pragma unroll
            for (int off = 16; off > 0; off >>= 1) {
                a += __shfl_down_sync(FULLW, a, off);
                c += __shfl_down_sync(FULLW, c, off);
            }
            if (lane == 0) {
                unsigned m = (unsigned)K - c;       // tie slots worth t each
                negsum = a + (double)m * (double)__uint_as_float(tbits);
            }
        }
    }

    // accumulate + last-CTA finalize & reset (for next graph replay)
    if (tid == 0) {
        if (negsum != 0.0) atomicAdd(&g_loss_c, negsum);
        __threadfence();
        unsigned t = atomicAdd(&g_ticket, 1u);
        if (t == (unsigned)B - 1u) {
            __threadfence();
            double L = atomicAdd(&g_loss_l, 0.0);
            double C = atomicAdd(&g_loss_c, 0.0);
            int    n = atomicAdd(&g_npos_total, 0);
            float nf = (float)n;
            out[0] = (float)L / nf;
            out[1] = (float)C / nf;
            g_loss_l = 0.0; g_loss_c = 0.0; g_npos_total = 0;
            for (int k = 0; k < MAXB; k++) g_npos_b[k] = 0;
            __threadfence();
            g_ticket = 0u;
        }
    }
}

// ---------------- launch ----------------
extern "C" void kernel_launch(void* const* d_in, const int* in_sizes, int n_in,
                              void* d_out, int out_size) {
    const float* loc     = (const float*)d_in[0];
    const float* conf    = (const float*)d_in[1];
    const float* targets = (const float*)d_in[2];
    const float* priors  = (const float*)d_in[3];
    int N = in_sizes[3] / 4;
    int B = in_sizes[0] / (4 * N);

    match_kernel<<<B, 512>>>(targets, priors, N);
    dim3 g((N + ROWS - 1) / ROWS, B);
    loss_kernel<<<g, ROWS>>>(loc, conf, targets, priors, N);
    select_kernel<<<B, 1024>>>(N, B, (float*)d_out);
}